// round 17
// baseline (speedup 1.0000x reference)
#include <cuda_runtime.h>
#include <cuda_fp16.h>
#include <math.h>

#define MAXN 100000
#define SLOT 64

// -------- scratch (device globals; no allocations allowed) --------
__device__ __half2 g_hw1h[MAXN * 32];    // h @ W1 fp16 (unscaled)
__device__ __half2 g_hw2h[MAXN * 16];    // dinv * (relu(conv1) @ W2), fp16
__device__ __half2 g_zh  [MAXN * 16];    // conv2 out z (fp16)
__device__ float   g_dinv[MAXN];
__device__ int     g_cnt [MAXN];         // in-degree AND fill cursor
__device__ __align__(16) int g_adj[MAXN * SLOT];  // fixed-slot adjacency
__device__ uint4   g_wihh4[192 * 8];     // Wih igo-packed fp16 [gatecol][k]
__device__ uint4   g_w1h4 [64 * 8];      // W1 fp16 [k][j]

// dynamic smem layout for k_lstm_mma (bytes):
//   sxh:   0      .. 18432   (128 rows x 72 halfs)
//   swi:   18432  .. 46080   (192 x 72 halfs)
//   sw1:   46080  .. 55296   (64 x 72 halfs)
//   sbs:   55296  .. 56064   (192 floats)
#define SMEM_LSTM_BYTES 56064

__device__ __forceinline__ float fast_sigmoid(float a) {
    return __fdividef(1.0f, 1.0f + __expf(-a));
}

__device__ __forceinline__ float fast_tanh(float a) {
    return 1.0f - __fdividef(2.0f, __expf(2.0f * a) + 1.0f);
}

__device__ __forceinline__ unsigned int sptr(const void* p) {
    return (unsigned int)__cvta_generic_to_shared(p);
}

__device__ __forceinline__ void ldsm_x4(unsigned int& r0, unsigned int& r1,
                                        unsigned int& r2, unsigned int& r3,
                                        unsigned int addr) {
    asm volatile("ldmatrix.sync.aligned.m8n8.x4.shared.b16 {%0,%1,%2,%3}, [%4];"
                 : "=r"(r0), "=r"(r1), "=r"(r2), "=r"(r3) : "r"(addr));
}

__device__ __forceinline__ void ldsm_x4t(unsigned int& r0, unsigned int& r1,
                                         unsigned int& r2, unsigned int& r3,
                                         unsigned int addr) {
    asm volatile("ldmatrix.sync.aligned.m8n8.x4.trans.shared.b16 {%0,%1,%2,%3}, [%4];"
                 : "=r"(r0), "=r"(r1), "=r"(r2), "=r"(r3) : "r"(addr));
}

__device__ __forceinline__ void mma16816(float* c,
    unsigned int a0, unsigned int a1, unsigned int a2, unsigned int a3,
    unsigned int b0, unsigned int b1) {
    asm volatile(
        "mma.sync.aligned.m16n8k16.row.col.f32.f16.f16.f32 "
        "{%0,%1,%2,%3}, {%4,%5,%6,%7}, {%8,%9}, {%0,%1,%2,%3};"
        : "+f"(c[0]), "+f"(c[1]), "+f"(c[2]), "+f"(c[3])
        : "r"(a0), "r"(a1), "r"(a2), "r"(a3), "r"(b0), "r"(b1));
}

// accumulate 8 halfs (one uint4) scaled by wgt into acc[8]
__device__ __forceinline__ void acc8w(float* acc, uint4 raw, float wgt) {
    float2 f0 = __half22float2(*(__half2*)&raw.x);
    float2 f1 = __half22float2(*(__half2*)&raw.y);
    float2 f2 = __half22float2(*(__half2*)&raw.z);
    float2 f3 = __half22float2(*(__half2*)&raw.w);
    acc[0] = fmaf(wgt, f0.x, acc[0]); acc[1] = fmaf(wgt, f0.y, acc[1]);
    acc[2] = fmaf(wgt, f1.x, acc[2]); acc[3] = fmaf(wgt, f1.y, acc[3]);
    acc[4] = fmaf(wgt, f2.x, acc[4]); acc[5] = fmaf(wgt, f2.y, acc[5]);
    acc[6] = fmaf(wgt, f3.x, acc[6]); acc[7] = fmaf(wgt, f3.y, acc[7]);
}

// accumulate 8 halfs unweighted (rows pre-scaled by dinv upstream)
__device__ __forceinline__ void add8(float* acc, uint4 raw) {
    float2 f0 = __half22float2(*(__half2*)&raw.x);
    float2 f1 = __half22float2(*(__half2*)&raw.y);
    float2 f2 = __half22float2(*(__half2*)&raw.z);
    float2 f3 = __half22float2(*(__half2*)&raw.w);
    acc[0] += f0.x; acc[1] += f0.y;
    acc[2] += f1.x; acc[3] += f1.y;
    acc[4] += f2.x; acc[5] += f2.y;
    acc[6] += f3.x; acc[7] += f3.y;
}

// -------- CSR zero + weight fp32 -> fp16 preconversion (fused) --------
__global__ void k_zerocvt(int n, const float* __restrict__ Wih,
                          const float* __restrict__ W1) {
    int i = blockIdx.x * blockDim.x + threadIdx.x;
    if (i < n) g_cnt[i] = 0;
    __half2* wih2 = (__half2*)g_wihh4;
    __half2* w12  = (__half2*)g_w1h4;
    if (i < 6144) {
        int mrow = i >> 5;
        int kp   = i & 31;
        int srow = (mrow < 64) ? mrow : (mrow + 64);  // skip dead f gate
        float2 v = ((const float2*)Wih)[srow * 32 + kp];
        wih2[i] = __floats2half2_rn(v.x, v.y);
    }
    int j = i - 6144;
    if (j >= 0 && j < 2048) {
        float2 v = ((const float2*)W1)[j];
        w12[j] = __floats2half2_rn(v.x, v.y);
    }
}

__global__ void k_fillcnt(const int* __restrict__ row, const int* __restrict__ col, int E) {
    int e = blockIdx.x * blockDim.x + threadIdx.x;
    if (e >= E) return;
    int c = col[e];
    int pos = atomicAdd(&g_cnt[c], 1);
    if (pos < SLOT) g_adj[c * SLOT + pos] = row[e];
}

__global__ void k_dinv(int n) {
    int i = blockIdx.x * blockDim.x + threadIdx.x;
    if (i < n) g_dinv[i] = rsqrtf((float)(g_cnt[i] + 1));
}

// ============ FUSED: LSTM step + h @ W1 -> hw1 fp16, via HMMA ==============
// Block = 128 rows, 512 thr (16 warps): warp = (mt 0..7, ng 0..1).
__global__ void __launch_bounds__(512) k_lstm_mma(
    const float* __restrict__ x,
    const float* __restrict__ bih, const float* __restrict__ bhh,
    __half2* __restrict__ Out, int n)
{
    extern __shared__ char dyn[];
    __half* sxh = (__half*)dyn;                  // 128 x 72
    __half* swi = (__half*)(dyn + 18432);        // 192 x 72
    __half* sw1 = (__half*)(dyn + 46080);        // 64 x 72
    float*  sbs = (float*)(dyn + 55296);         // 192

    const int t    = threadIdx.x;
    const int lane = t & 31;
    const int wrp  = t >> 5;
    const int br   = blockIdx.x * 128;
    const int mt   = wrp & 7;
    const int ng   = wrp >> 3;

    // ---- x: global fp32 -> smem fp16, packed uint4 stores ----
    for (int p = 0; p < 2; p++) {
        int d = p * 512 + t;                 // 0..1023 = 128 rows x 8 uint4
        int row = d >> 3;
        int q   = d & 7;
        float4 va = make_float4(0.f, 0.f, 0.f, 0.f);
        float4 vb = make_float4(0.f, 0.f, 0.f, 0.f);
        if (br + row < n) {
            const float4* src = (const float4*)x + (size_t)(br + row) * 16 + q * 2;
            va = src[0];
            vb = src[1];
        }
        __half2 h0 = __floats2half2_rn(va.x, va.y);
        __half2 h1 = __floats2half2_rn(va.z, va.w);
        __half2 h2 = __floats2half2_rn(vb.x, vb.y);
        __half2 h3 = __floats2half2_rn(vb.z, vb.w);
        uint4 u;
        u.x = *(unsigned int*)&h0;
        u.y = *(unsigned int*)&h1;
        u.z = *(unsigned int*)&h2;
        u.w = *(unsigned int*)&h3;
        *(uint4*)&sxh[row * 72 + q * 8] = u;
    }
    // ---- weights: pre-converted fp16 -> smem (uint4 copies) ----
    for (int p = 0; p < 3; p++) {
        int idx = p * 512 + t;               // 0..1535
        int r = idx >> 3;
        int q = idx & 7;
        *(uint4*)&swi[r * 72 + q * 8] = g_wihh4[idx];
    }
    if (t < 512) {
        int idx = t;                         // 0..511
        int r = idx >> 3;
        int q = idx & 7;
        *(uint4*)&sw1[r * 72 + q * 8] = g_w1h4[idx];
    }
    if (t < 192) {
        int jj = (t < 64) ? t : (t + 64);
        sbs[t] = bih[jj] + bhh[jj];
    }
    __syncthreads();

    // ---- ldmatrix lane addressing ----
    const int bgrp = lane >> 3;
    const int lr   = lane & 7;
    const int arow  = mt * 16 + lr + (((bgrp & 1) != 0) ? 8 : 0);
    const int acolh = (bgrp >> 1) * 8;
    const unsigned int abase = sptr(&sxh[arow * 72 + acolh]);
    const unsigned int bb1 = sptr(swi)
        + (unsigned int)(((((bgrp >> 1) * 8) + lr) * 72 + (bgrp & 1) * 8) * 2);
    const unsigned int bb2 = sptr(sw1)
        + (unsigned int)(((((bgrp & 1) * 8) + lr) * 72 + (bgrp >> 1) * 8) * 2);

    // ---- phase 1: 12 output tiles (3 gates x 4 n8-tiles), K = 4 x k16 ----
    float acc[12][4];
    for (int i = 0; i < 12; i++) {
        acc[i][0] = 0.f; acc[i][1] = 0.f; acc[i][2] = 0.f; acc[i][3] = 0.f;
    }
    for (int kk = 0; kk < 4; kk++) {
        unsigned int a0, a1, a2, a3;
        ldsm_x4(a0, a1, a2, a3, abase + (unsigned int)(kk * 32));
        for (int g = 0; g < 3; g++) {
            for (int np = 0; np < 2; np++) {
                int n0 = g * 64 + ng * 32 + np * 16;
                unsigned int b0, b1, b2, b3;
                ldsm_x4(b0, b1, b2, b3, bb1 + (unsigned int)(n0 * 144 + kk * 32));
                mma16816(acc[g * 4 + np * 2],     a0, a1, a2, a3, b0, b1);
                mma16816(acc[g * 4 + np * 2 + 1], a0, a1, a2, a3, b2, b3);
            }
        }
    }
    __syncthreads();

    // ---- activations -> h (fp16) back into sxh ----
    const int qr = lane >> 2;
    const int qc = (lane & 3) * 2;
    for (int nb = 0; nb < 4; nb++) {
        int cb = ng * 32 + nb * 8 + qc;
        float bi0 = sbs[cb];
        float bi1 = sbs[cb + 1];
        float bg0 = sbs[64 + cb];
        float bg1 = sbs[64 + cb + 1];
        float bo0 = sbs[128 + cb];
        float bo1 = sbs[128 + cb + 1];
        float* ci = acc[nb];
        float* cg = acc[4 + nb];
        float* co = acc[8 + nb];
        float h00 = fast_sigmoid(co[0] + bo0) *
                    fast_tanh(fast_sigmoid(ci[0] + bi0) * fast_tanh(cg[0] + bg0));
        float h01 = fast_sigmoid(co[1] + bo1) *
                    fast_tanh(fast_sigmoid(ci[1] + bi1) * fast_tanh(cg[1] + bg1));
        float h10 = fast_sigmoid(co[2] + bo0) *
                    fast_tanh(fast_sigmoid(ci[2] + bi0) * fast_tanh(cg[2] + bg0));
        float h11 = fast_sigmoid(co[3] + bo1) *
                    fast_tanh(fast_sigmoid(ci[3] + bi1) * fast_tanh(cg[3] + bg1));
        int r0 = mt * 16 + qr;
        *(__half2*)&sxh[r0 * 72 + cb]       = __floats2half2_rn(h00, h01);
        *(__half2*)&sxh[(r0 + 8) * 72 + cb] = __floats2half2_rn(h10, h11);
    }
    __syncthreads();

    // ---- phase 2: hw1 = h @ W1 (4 n8-tiles per warp) ----
    float acc2[4][4];
    for (int i = 0; i < 4; i++) {
        acc2[i][0] = 0.f; acc2[i][1] = 0.f; acc2[i][2] = 0.f; acc2[i][3] = 0.f;
    }
    for (int kk = 0; kk < 4; kk++) {
        unsigned int a0, a1, a2, a3;
        ldsm_x4(a0, a1, a2, a3, abase + (unsigned int)(kk * 32));
        for (int np = 0; np < 2; np++) {
            int n0 = ng * 32 + np * 16;
            unsigned int b0, b1, b2, b3;
            ldsm_x4t(b0, b1, b2, b3, bb2 + (unsigned int)(kk * 2304 + n0 * 2));
            mma16816(acc2[np * 2],     a0, a1, a2, a3, b0, b1);
            mma16816(acc2[np * 2 + 1], a0, a1, a2, a3, b2, b3);
        }
    }

    // ---- store hw1 fp16 ----
    for (int nb = 0; nb < 4; nb++) {
        int col = ng * 32 + nb * 8 + qc;
        int rg0 = br + mt * 16 + qr;
        if (rg0 < n) {
            Out[(size_t)rg0 * 32 + (col >> 1)] =
                __floats2half2_rn(acc2[nb][0], acc2[nb][1]);
        }
        if (rg0 + 8 < n) {
            Out[(size_t)(rg0 + 8) * 32 + (col >> 1)] =
                __floats2half2_rn(acc2[nb][2], acc2[nb][3]);
        }
    }
}

// ========== FUSED: conv1 pull (weighted gather) + h2 @ W2 -> hw2' fp16 =====
__global__ void __launch_bounds__(256) k_pullgemm(
    const __half2* __restrict__ HW1, const float* __restrict__ b1,
    const float* __restrict__ W2, __half2* __restrict__ OutH, int n)
{
    __shared__ float w2s[64][32];
    __shared__ float hs[32][68];

    const int t  = threadIdx.x;
    const int nl = t >> 3;
    const int j  = t & 7;
    const int v  = blockIdx.x * 32 + nl;
    const bool alive = (v < n);

    for (int p = 0; p < 2; p++) {
        ((float4*)w2s)[p * 256 + t] = ((const float4*)W2)[p * 256 + t];
    }

    const int s0 = v * SLOT;
    int deg = alive ? g_cnt[v] : 0;
    if (deg > SLOT) deg = SLOT;
    const uint4* HW4 = (const uint4*)HW1;

    float acc[8];
    for (int i = 0; i < 8; i++) acc[i] = 0.f;

    const int e4 = s0 + (deg & ~3);
    int k = s0;
    if (k < e4) {
        int4 idx = *(const int4*)(g_adj + k);
        while (k < e4) {
            k += 4;
            int4 nidx;
            if (k < e4) nidx = *(const int4*)(g_adj + k);
            float w0 = g_dinv[idx.x];
            float w1 = g_dinv[idx.y];
            float w2 = g_dinv[idx.z];
            float w3 = g_dinv[idx.w];
            uint4 a0 = HW4[(size_t)idx.x * 8 + j];
            uint4 a1 = HW4[(size_t)idx.y * 8 + j];
            uint4 a2 = HW4[(size_t)idx.z * 8 + j];
            uint4 a3 = HW4[(size_t)idx.w * 8 + j];
            acc8w(acc, a0, w0);
            acc8w(acc, a1, w1);
            acc8w(acc, a2, w2);
            acc8w(acc, a3, w3);
            idx = nidx;
        }
    }
    for (int kk = e4; kk < s0 + deg; kk++) {
        int r = g_adj[kk];
        acc8w(acc, HW4[(size_t)r * 8 + j], g_dinv[r]);
    }

    float dv = alive ? g_dinv[v] : 0.f;
    {
        float sl = dv * dv;
        uint4 raw;
        raw.x = 0u; raw.y = 0u; raw.z = 0u; raw.w = 0u;
        if (alive) raw = HW4[(size_t)v * 8 + j];
        float2 s0f = __half22float2(*(__half2*)&raw.x);
        float2 s1f = __half22float2(*(__half2*)&raw.y);
        float2 s2f = __half22float2(*(__half2*)&raw.z);
        float2 s3f = __half22float2(*(__half2*)&raw.w);
        float slf[8];
        slf[0] = s0f.x; slf[1] = s0f.y; slf[2] = s1f.x; slf[3] = s1f.y;
        slf[4] = s2f.x; slf[5] = s2f.y; slf[6] = s3f.x; slf[7] = s3f.y;
        for (int i = 0; i < 8; i++) {
            hs[nl][j * 8 + i] =
                fmaxf(fmaf(dv, acc[i], fmaf(sl, slf[i], b1[j * 8 + i])), 0.f);
        }
    }
    __syncthreads();

    const int j0 = j * 4;
    float g0 = 0.f;
    float g1 = 0.f;
    float g2 = 0.f;
    float g3 = 0.f;
    for (int k4 = 0; k4 < 16; k4++) {
        float4 h4 = *(const float4*)&hs[nl][k4 * 4];
        float4 wa = *(const float4*)&w2s[k4 * 4 + 0][j0];
        float4 wb = *(const float4*)&w2s[k4 * 4 + 1][j0];
        float4 wc = *(const float4*)&w2s[k4 * 4 + 2][j0];
        float4 wd = *(const float4*)&w2s[k4 * 4 + 3][j0];
        g0 = fmaf(h4.x, wa.x, g0); g0 = fmaf(h4.y, wb.x, g0);
        g0 = fmaf(h4.z, wc.x, g0); g0 = fmaf(h4.w, wd.x, g0);
        g1 = fmaf(h4.x, wa.y, g1); g1 = fmaf(h4.y, wb.y, g1);
        g1 = fmaf(h4.z, wc.y, g1); g1 = fmaf(h4.w, wd.y, g1);
        g2 = fmaf(h4.x, wa.z, g2); g2 = fmaf(h4.y, wb.z, g2);
        g2 = fmaf(h4.z, wc.z, g2); g2 = fmaf(h4.w, wd.z, g2);
        g3 = fmaf(h4.x, wa.w, g3); g3 = fmaf(h4.y, wb.w, g3);
        g3 = fmaf(h4.z, wc.w, g3); g3 = fmaf(h4.w, wd.w, g3);
    }

    if (alive) {
        __half2* drow = OutH + (size_t)v * 16 + j * 2;
        drow[0] = __floats2half2_rn(dv * g0, dv * g1);
        drow[1] = __floats2half2_rn(dv * g2, dv * g3);
    }
}

// ========== CSR pull, 32 feats (pre-scaled hw2'): 4 lanes/node ========
__global__ void __launch_bounds__(256) k_pull32(
    const __half2* __restrict__ HW, const float* __restrict__ bias,
    __half2* __restrict__ Out, int n)
{
    const int t = threadIdx.x;
    const int v = blockIdx.x * 64 + t / 4;
    const int j = t % 4;
    if (v >= n) return;

    const int s0 = v * SLOT;
    int deg = g_cnt[v];
    if (deg > SLOT) deg = SLOT;
    const uint4* HW4 = (const uint4*)HW;

    float acc[8];
    for (int i = 0; i < 8; i++) acc[i] = 0.f;

    const int e4 = s0 + (deg & ~3);
    int k = s0;
    if (k < e4) {
        int4 idx = *(const int4*)(g_adj + k);
        while (k < e4) {
            k += 4;
            int4 nidx;
            if (k < e4) nidx = *(const int4*)(g_adj + k);
            uint4 a0 = HW4[(size_t)idx.x * 4 + j];
            uint4 a1 = HW4[(size_t)idx.y * 4 + j];
            uint4 a2 = HW4[(size_t)idx.z * 4 + j];
            uint4 a3 = HW4[(size_t)idx.w * 4 + j];
            add8(acc, a0);
            add8(acc, a1);
            add8(acc, a2);
            add8(acc, a3);
            idx = nidx;
        }
    }
    for (int kk = e4; kk < s0 + deg; kk++) {
        int r = g_adj[kk];
        add8(acc, HW4[(size_t)r * 4 + j]);
    }

    float dv = g_dinv[v];
    add8(acc, HW4[(size_t)v * 4 + j]);

    float o[8];
    for (int i = 0; i < 8; i++) {
        o[i] = fmaf(dv, acc[i], bias[j * 8 + i]);
    }

    __half2* drow = Out + (size_t)v * 16 + j * 4;
    drow[0] = __floats2half2_rn(o[0], o[1]);
    drow[1] = __floats2half2_rn(o[2], o[3]);
    drow[2] = __floats2half2_rn(o[4], o[5]);
    drow[3] = __floats2half2_rn(o[6], o[7]);
}

// -------- edge dot over fp16 z rows; 4 lanes/edge --------
__global__ void k_edot(const int* __restrict__ eli, float* __restrict__ out, int EL)
{
    int gid = blockIdx.x * blockDim.x + threadIdx.x;
    if (gid >= EL * 4) return;
    int e = gid >> 2;
    int j = gid & 3;
    int s = eli[e];
    int d = eli[EL + e];
    const uint4* Z = (const uint4*)g_zh;
    uint4 a = Z[(size_t)s * 4 + j];
    uint4 b = Z[(size_t)d * 4 + j];
    float p = 0.f;
    {
        float2 fa, fb;
        fa = __half22float2(*(__half2*)&a.x);
        fb = __half22float2(*(__half2*)&b.x);
        p = fmaf(fa.x, fb.x, p); p = fmaf(fa.y, fb.y, p);
        fa = __half22float2(*(__half2*)&a.y);
        fb = __half22float2(*(__half2*)&b.y);
        p = fmaf(fa.x, fb.x, p); p = fmaf(fa.y, fb.y, p);
        fa = __half22float2(*(__half2*)&a.z);
        fb = __half22float2(*(__half2*)&b.z);
        p = fmaf(fa.x, fb.x, p); p = fmaf(fa.y, fb.y, p);
        fa = __half22float2(*(__half2*)&a.w);
        fb = __half22float2(*(__half2*)&b.w);
        p = fmaf(fa.x, fb.x, p); p = fmaf(fa.y, fb.y, p);
    }
    p += __shfl_down_sync(0xffffffffu, p, 2);
    p += __shfl_down_sync(0xffffffffu, p, 1);
    if (j == 0) out[e] = p;
}

extern "C" void kernel_launch(void* const* d_in, const int* in_sizes, int n_in,
                              void* d_out, int out_size)
{
    (void)n_in; (void)out_size;
    const float* x   = (const float*)d_in[0];
    const int*   ei  = (const int*)  d_in[1];
    const int*   eli = (const int*)  d_in[2];
    const float* Wih = (const float*)d_in[3];
    const float* bih = (const float*)d_in[5];
    const float* bhh = (const float*)d_in[6];
    const float* W1  = (const float*)d_in[7];
    const float* b1  = (const float*)d_in[8];
    const float* W2  = (const float*)d_in[9];
    const float* b2  = (const float*)d_in[10];
    float* out = (float*)d_out;

    int n  = in_sizes[0] / 64;
    int E  = in_sizes[1] / 2;
    int EL = in_sizes[2] / 2;
    const int* row = ei;
    const int* col = ei + E;

    __half2* p_hw1 = 0;
    __half2* p_hw2 = 0;
    __half2* p_z   = 0;
    cudaGetSymbolAddress((void**)&p_hw1, g_hw1h);
    cudaGetSymbolAddress((void**)&p_hw2, g_hw2h);
    cudaGetSymbolAddress((void**)&p_z,   g_zh);

    static cudaStream_t s2 = 0;
    static cudaEvent_t evFork = 0;
    static cudaEvent_t evW = 0;
    static cudaEvent_t evJoin = 0;
    if (s2 == 0) {
        cudaStreamCreateWithFlags(&s2, cudaStreamNonBlocking);
        cudaEventCreateWithFlags(&evFork, cudaEventDisableTiming);
        cudaEventCreateWithFlags(&evW, cudaEventDisableTiming);
        cudaEventCreateWithFlags(&evJoin, cudaEventDisableTiming);
        cudaFuncSetAttribute(k_lstm_mma,
                             cudaFuncAttributeMaxDynamicSharedMemorySize,
                             SMEM_LSTM_BYTES);
    }

    const int T = 256;

    // ---- fork: CSR build + weight cvt on s2; HMMA LSTM+W1 on main ----
    cudaEventRecord(evFork, 0);
    cudaStreamWaitEvent(s2, evFork, 0);

    k_zerocvt<<<(n + T - 1) / T, T, 0, s2>>>(n, Wih, W1);
    cudaEventRecord(evW, s2);
    k_fillcnt<<<(E + T - 1) / T, T, 0, s2>>>(row, col, E);
    k_dinv   <<<(n + T - 1) / T, T, 0, s2>>>(n);
    cudaEventRecord(evJoin, s2);

    cudaStreamWaitEvent(0, evW, 0);
    k_lstm_mma<<<(n + 127) / 128, 512, SMEM_LSTM_BYTES>>>(x, bih, bhh, p_hw1, n);

    // ---- join ----
    cudaStreamWaitEvent(0, evJoin, 0);

    k_pullgemm<<<(n + 31) / 32, 256>>>(p_hw1, b1, W2, p_hw2, n);
    k_pull32  <<<(n + 63) / 64, 256>>>(p_hw2, b2, p_z, n);
    k_edot    <<<(EL * 4 + T - 1) / T, T>>>(eli, out, EL);
}